// round 7
// baseline (speedup 1.0000x reference)
#include <cuda_runtime.h>
#include <cuda_fp16.h>
#include <cstdint>

#define DIM    256
#define HW     1024
#define NTOT   32768
#define KCODES 1024
#define MTILE  128
#define NBLOCKS (NTOT / MTILE)          // 256
#define ZQ_ELEMS  ((size_t)NTOT * DIM)
#define CODES_OFF ZQ_ELEMS
#define LOSS_OFF  (ZQ_ELEMS + (size_t)NTOT)

#define AKP   132                        // A row stride in half2 words (128+4)
#define BSTRH 20                         // B row stride in half2 words (16+4)

// dynamic smem layout in 4B words
#define OFF_AHI 0                        // 128*132 = 16896
#define OFF_ALO 16896
#define OFF_B   33792                    // 2 bufs x (hi 2560 + lo 2560)
#define BBUF_W  5120
#define OFF_ES  44032
#define OFF_RV  45056
#define OFF_RI  45312
#define OFF_RED 45568
#define SMEM_WORDS 45576
#define SMEM_BYTES (SMEM_WORDS * 4)      // 182304

__device__ __half g_ehi[(size_t)KCODES * DIM];
__device__ __half g_elo[(size_t)KCODES * DIM];
__device__ float  g_enorm[KCODES];
__device__ float  g_partials[NBLOCKS];

__device__ __forceinline__ uint32_t smem_u32(const void* p) {
    uint32_t a;
    asm("{ .reg .u64 t; cvta.to.shared.u64 t, %1; cvt.u32.u64 %0, t; }" : "=r"(a) : "l"(p));
    return a;
}
// pack two fp32 -> half2 {lo half=x0, hi half=x1} + residual pair
__device__ __forceinline__ void split2(float x0, float x1, uint32_t& h2, uint32_t& l2) {
    asm("cvt.rn.f16x2.f32 %0, %1, %2;" : "=r"(h2) : "f"(x1), "f"(x0));
    float f0, f1;
    asm("{ .reg .b16 l,h; mov.b32 {l,h}, %2; cvt.f32.f16 %0, l; cvt.f32.f16 %1, h; }"
        : "=f"(f0), "=f"(f1) : "r"(h2));
    asm("cvt.rn.f16x2.f32 %0, %1, %2;" : "=r"(l2) : "f"(x1 - f1), "f"(x0 - f0));
}

#define MMA16(c, a, b0, b1)                                                   \
    asm volatile("mma.sync.aligned.m16n8k16.row.col.f32.f16.f16.f32 "         \
        "{%0,%1,%2,%3}, {%4,%5,%6,%7}, {%8,%9}, {%0,%1,%2,%3};"               \
        : "+f"((c)[0]), "+f"((c)[1]), "+f"((c)[2]), "+f"((c)[3])              \
        : "r"((a)[0]), "r"((a)[1]), "r"((a)[2]), "r"((a)[3]),                 \
          "r"(b0), "r"(b1))

#define LDSM4(r0, r1, r2, r3, addr)                                           \
    asm volatile("ldmatrix.sync.aligned.m8n8.x4.shared.b16 {%0,%1,%2,%3}, [%4];" \
        : "=r"(r0), "=r"(r1), "=r"(r2), "=r"(r3) : "r"(addr))

#define CPA16(dst, src) \
    asm volatile("cp.async.cg.shared.global [%0], [%1], 16;" :: "r"(dst), "l"(src) : "memory")
#define CP_COMMIT() asm volatile("cp.async.commit_group;" ::: "memory")
#define CP_WAIT0()  asm volatile("cp.async.wait_group 0;" ::: "memory")

// ---------------- prepass: split emb -> g_ehi/g_elo (+ ||e||^2) ----------------
__global__ void vq_split(const float* __restrict__ emb) {
    int gw = (blockIdx.x * blockDim.x + threadIdx.x) >> 5, lane = threadIdx.x & 31;
    if (gw >= KCODES) return;
    const float* row = emb + (size_t)gw * DIM;
    const int d0 = lane * 8;
    float4 v0 = *reinterpret_cast<const float4*>(row + d0);
    float4 v1 = *reinterpret_cast<const float4*>(row + d0 + 4);
    uint4 h, l;
    split2(v0.x, v0.y, h.x, l.x);
    split2(v0.z, v0.w, h.y, l.y);
    split2(v1.x, v1.y, h.z, l.z);
    split2(v1.z, v1.w, h.w, l.w);
    *reinterpret_cast<uint4*>(g_ehi + (size_t)gw * DIM + d0) = h;
    *reinterpret_cast<uint4*>(g_elo + (size_t)gw * DIM + d0) = l;
    float s = v0.x*v0.x + v0.y*v0.y + v0.z*v0.z + v0.w*v0.w
            + v1.x*v1.x + v1.y*v1.y + v1.z*v1.z + v1.w*v1.w;
    #pragma unroll
    for (int o = 16; o; o >>= 1) s += __shfl_xor_sync(0xFFFFFFFFu, s, o);
    if (lane == 0) g_enorm[gw] = s;
}

// issue cp.async for one B chunk (128 codes x 32 dims, hi+lo) into buffer
__device__ __forceinline__ void b_cpa(int c, uint32_t dstbyte, int tid) {
    const int nc = c >> 3, dc = c & 7;
    const __half* srcH = g_ehi + (size_t)(nc * 128) * DIM + dc * 32;
    const __half* srcL = g_elo + (size_t)(nc * 128) * DIM + dc * 32;
    #pragma unroll
    for (int i = 0; i < 2; i++) {
        int idx = tid + i * 256;              // 0..511
        int n = idx >> 2, j = idx & 3;
        uint32_t d = dstbyte + n * (BSTRH * 4) + j * 16;
        CPA16(d, srcH + (size_t)n * DIM + j * 8);
        CPA16(d + BBUF_W * 2, srcL + (size_t)n * DIM + j * 8);   // lo at +2560 words
    }
    CP_COMMIT();
}

// ---------------- main ----------------
__global__ __launch_bounds__(256, 1)
void vq_main(const float* __restrict__ z, const float* __restrict__ emb,
             float* __restrict__ out) {
    extern __shared__ __align__(16) uint32_t sw[];
    uint32_t* sAhi = sw + OFF_AHI;
    uint32_t* sAlo = sw + OFF_ALO;
    float*    es   = reinterpret_cast<float*>(sw + OFF_ES);
    float*    rv   = reinterpret_cast<float*>(sw + OFF_RV);
    int*      ri   = reinterpret_cast<int*>(sw + OFF_RI);
    float*    red  = reinterpret_cast<float*>(sw + OFF_RED);

    const int tid = threadIdx.x, wid = tid >> 5, lane = tid & 31;
    const int wm = wid & 3, wn = wid >> 2;          // 4 m-warps x 2 n-warps
    const int tig = lane & 3, grp = lane >> 2;

    const int n0 = blockIdx.x * MTILE;
    const int b = n0 >> 10, hw0 = n0 & (HW - 1);
    const float* zbase = z + (size_t)b * DIM * HW + hw0;

    const uint32_t sbase = smem_u32(sw);
    const uint32_t bBufByte = sbase + OFF_B * 4;

    // prologue: start chunk 0 into buf 0
    b_cpa(0, bBufByte, tid);

    // ---- split A tile (256k x 128m) into Ahi/Alo half2 [m][kp] ----
    {
        const int m = tid & 127, kh = (tid >> 7) * 128;
        const float* zc = zbase + m;
        uint32_t* ah = sAhi + m * AKP + (kh >> 1);
        uint32_t* al = sAlo + m * AKP + (kh >> 1);
        #pragma unroll 4
        for (int j = 0; j < 64; j++) {
            const int k = kh + 2 * j;
            float x0 = zc[(size_t)k * HW], x1 = zc[(size_t)(k + 1) * HW];
            uint32_t h2, l2;
            split2(x0, x1, h2, l2);
            ah[j] = h2; al[j] = l2;
        }
    }
    for (int i = tid; i < KCODES; i += 256) es[i] = g_enorm[i];

    // per-lane ldmatrix base addresses
    const int mrow = wm * 32 + ((lane >> 3) & 1) * 8 + (lane & 7);
    const uint32_t aAddrH = sbase + mrow * (AKP * 4) + (lane >> 4) * 16;   // +OFF_AHI*4 = 0
    const uint32_t aAddrL = aAddrH + OFF_ALO * 4;
    const int nrow = wn * 64 + ((lane >> 4) << 3) + (lane & 7);
    const uint32_t bAddr0 = bBufByte + nrow * (BSTRH * 4) + ((lane >> 3) & 1) * 16;

    float bestv[4]; int besti[4];
    #pragma unroll
    for (int r = 0; r < 4; r++) { bestv[r] = 3.4e38f; besti[r] = 0; }

    float acc[2][8][4];

    #pragma unroll 1
    for (int c = 0; c < 64; c++) {
        const int nc = c >> 3, dc = c & 7, s = c & 1;
        CP_WAIT0();
        __syncthreads();
        if (c < 63) b_cpa(c + 1, bBufByte + (s ^ 1) * (BBUF_W * 4), tid);

        if (dc == 0) {
            #pragma unroll
            for (int mt = 0; mt < 2; mt++)
                #pragma unroll
                for (int nt = 0; nt < 8; nt++)
                    #pragma unroll
                    for (int q = 0; q < 4; q++) acc[mt][nt][q] = 0.f;
        }

        #pragma unroll
        for (int kk = 0; kk < 2; kk++) {
            const uint32_t ak = dc * 64 + kk * 32;      // k byte offset in A rows
            uint32_t ah[2][4], al[2][4];
            #pragma unroll
            for (int mt = 0; mt < 2; mt++) {
                LDSM4(ah[mt][0], ah[mt][1], ah[mt][2], ah[mt][3], aAddrH + mt * (16 * AKP * 4) + ak);
                LDSM4(al[mt][0], al[mt][1], al[mt][2], al[mt][3], aAddrL + mt * (16 * AKP * 4) + ak);
            }
            const uint32_t bk = s * (BBUF_W * 4) + kk * 32;   // FIX: 16 halves = 32 bytes
            #pragma unroll
            for (int ntp = 0; ntp < 4; ntp++) {
                uint32_t bh[4], bl[4];
                const uint32_t ba = bAddr0 + bk + ntp * (16 * BSTRH * 4);
                LDSM4(bh[0], bh[1], bh[2], bh[3], ba);
                LDSM4(bl[0], bl[1], bl[2], bl[3], ba + BBUF_W * 2);
                #pragma unroll
                for (int half = 0; half < 2; half++) {
                    const int nt = ntp * 2 + half;
                    const uint32_t bh0 = bh[half * 2], bh1 = bh[half * 2 + 1];
                    const uint32_t bl0 = bl[half * 2], bl1 = bl[half * 2 + 1];
                    #pragma unroll
                    for (int mt = 0; mt < 2; mt++) {
                        MMA16(acc[mt][nt], ah[mt], bh0, bh1);
                        MMA16(acc[mt][nt], ah[mt], bl0, bl1);
                        MMA16(acc[mt][nt], al[mt], bh0, bh1);
                    }
                }
            }
        }

        if (dc == 7) {
            // fused argmin (ascending n, strict < => first-min tie-break)
            #pragma unroll
            for (int nt = 0; nt < 8; nt++) {
                const int n = nc * 128 + wn * 64 + nt * 8 + tig * 2;
                const float e0 = es[n], e1 = es[n + 1];
                #pragma unroll
                for (int mt = 0; mt < 2; mt++) {
                    float s0 = fmaf(-2.f, acc[mt][nt][0], e0);
                    float s1 = fmaf(-2.f, acc[mt][nt][1], e1);
                    float s2 = fmaf(-2.f, acc[mt][nt][2], e0);
                    float s3 = fmaf(-2.f, acc[mt][nt][3], e1);
                    const int r0 = mt * 2, r1 = mt * 2 + 1;
                    if (s0 < bestv[r0]) { bestv[r0] = s0; besti[r0] = n; }
                    if (s1 < bestv[r0]) { bestv[r0] = s1; besti[r0] = n + 1; }
                    if (s2 < bestv[r1]) { bestv[r1] = s2; besti[r1] = n; }
                    if (s3 < bestv[r1]) { bestv[r1] = s3; besti[r1] = n + 1; }
                }
            }
        }
    }

    // reduce across the 4 tig-lanes sharing each row
    #pragma unroll
    for (int r = 0; r < 4; r++) {
        float v = bestv[r]; int ix = besti[r];
        #pragma unroll
        for (int o = 1; o <= 2; o <<= 1) {
            float ov = __shfl_xor_sync(0xFFFFFFFFu, v, o);
            int   oi = __shfl_xor_sync(0xFFFFFFFFu, ix, o);
            if (ov < v || (ov == v && oi < ix)) { v = ov; ix = oi; }
        }
        if (tig == 0) {
            const int mt = r >> 1, rh = r & 1;
            const int row = wm * 32 + mt * 16 + rh * 8 + grp;
            rv[wn * 128 + row] = v;
            ri[wn * 128 + row] = ix;
        }
    }
    __syncthreads();

    if (tid < 128) {
        float v0 = rv[tid], v1 = rv[128 + tid];
        int i0 = ri[tid], i1 = ri[128 + tid];
        int code = (v1 < v0 || (v1 == v0 && i1 < i0)) ? i1 : i0;
        ri[tid] = code;
        out[CODES_OFF + n0 + tid] = (float)code;
    }
    __syncthreads();

    // gather z_q + loss
    const int nl = tid & 127, half = tid >> 7;
    const int code = ri[nl];
    const float4* er = reinterpret_cast<const float4*>(emb + (size_t)code * DIM);
    float* zq = out + (size_t)b * DIM * HW + hw0 + nl;
    const float* zr = zbase + nl;
    float lsum = 0.f;
    #pragma unroll 4
    for (int d4 = half; d4 < 64; d4 += 2) {
        float4 e = __ldg(er + d4);
        const int o0 = (d4 * 4) * HW;
        float z0 = zr[o0], z1 = zr[o0 + HW], z2 = zr[o0 + 2 * HW], z3 = zr[o0 + 3 * HW];
        zq[o0] = e.x; zq[o0 + HW] = e.y; zq[o0 + 2 * HW] = e.z; zq[o0 + 3 * HW] = e.w;
        float d0 = e.x - z0, d1 = e.y - z1, d2 = e.z - z2, d3 = e.w - z3;
        lsum = fmaf(d0, d0, lsum); lsum = fmaf(d1, d1, lsum);
        lsum = fmaf(d2, d2, lsum); lsum = fmaf(d3, d3, lsum);
    }
    #pragma unroll
    for (int o = 16; o; o >>= 1) lsum += __shfl_xor_sync(0xFFFFFFFFu, lsum, o);
    if (lane == 0) red[wid] = lsum;
    __syncthreads();
    if (tid == 0) {
        float s = 0.f;
        #pragma unroll
        for (int w = 0; w < 8; w++) s += red[w];
        g_partials[blockIdx.x] = s;
    }
}

// ---------------- finalize ----------------
__global__ void vq_fin(float* __restrict__ out) {
    if (threadIdx.x == 0 && blockIdx.x == 0) {
        float s = 0.f;
        for (int i = 0; i < NBLOCKS; i++) s += g_partials[i];
        out[LOSS_OFF] = 1.25f * s / (float)ZQ_ELEMS;
    }
}

extern "C" void kernel_launch(void* const* d_in, const int* in_sizes, int n_in,
                              void* d_out, int out_size) {
    const float* z   = (const float*)d_in[0];
    const float* emb = (const float*)d_in[1];
    if (n_in >= 2 && in_sizes[0] == KCODES * DIM) { const float* t = z; z = emb; emb = t; }
    float* out = (float*)d_out;

    cudaFuncSetAttribute(vq_main, cudaFuncAttributeMaxDynamicSharedMemorySize, SMEM_BYTES);
    vq_split<<<(KCODES * 32 + 255) / 256, 256>>>(emb);
    vq_main<<<NBLOCKS, 256, SMEM_BYTES>>>(z, emb, out);
    vq_fin<<<1, 32>>>(out);
}

// round 8
// speedup vs baseline: 1.2241x; 1.2241x over previous
#include <cuda_runtime.h>
#include <cuda_fp16.h>
#include <cstdint>

#define DIM    256
#define HW     1024
#define NTOT   32768
#define KCODES 1024
#define MT     128
#define GBLOCKS (NTOT / MT)              // 256
#define ZQ_ELEMS  ((size_t)NTOT * DIM)
#define CODES_OFF ZQ_ELEMS
#define LOSS_OFF  (ZQ_ELEMS + (size_t)NTOT)

// gemm smem layout (4B words)
#define AKPW 132                          // A row: 256 halves + 8 pad = 528B (16 mod 128)
#define BKPW 68                           // B row: 128 halves + 8 pad = 272B (16 mod 128)
#define OFF_A  0                          // 128*132 = 16896
#define OFF_B  16896                      // 2 stages x 128*68 = 17408
#define BSTG_W 8704
#define OFF_C  34304                      // 8704
#define OFF_ES 43008                      // 1024
#define SMEM_WORDS 44032
#define SMEM_BYTES (SMEM_WORDS * 4)       // 176128

// window constants (rigorous bounds + slack)
#define C1W 5.2e-4f
#define C2W 5.0e-4f
#define C3W 0.06f

__device__ __half g_zh[(size_t)NTOT * DIM];
__device__ __half g_zl[(size_t)NTOT * DIM];
__device__ __half g_eh[(size_t)KCODES * DIM];
__device__ __half g_el[(size_t)KCODES * DIM];
__device__ float  g_en2[KCODES];
__device__ __half g_c16[(size_t)NTOT * KCODES];   // 64MB score buffer
__device__ int    g_codes[NTOT];
__device__ float  g_partials[GBLOCKS];

__device__ __forceinline__ uint32_t smem_u32(const void* p) {
    uint32_t a;
    asm("{ .reg .u64 t; cvta.to.shared.u64 t, %1; cvt.u32.u64 %0, t; }" : "=r"(a) : "l"(p));
    return a;
}
__device__ __forceinline__ void split2(float x0, float x1, uint32_t& h2, uint32_t& l2) {
    asm("cvt.rn.f16x2.f32 %0, %1, %2;" : "=r"(h2) : "f"(x1), "f"(x0));
    float f0, f1;
    asm("{ .reg .b16 l,h; mov.b32 {l,h}, %2; cvt.f32.f16 %0, l; cvt.f32.f16 %1, h; }"
        : "=f"(f0), "=f"(f1) : "r"(h2));
    asm("cvt.rn.f16x2.f32 %0, %1, %2;" : "=r"(l2) : "f"(x1 - f1), "f"(x0 - f0));
}

#define MMA16(c, a, b0, b1)                                                   \
    asm volatile("mma.sync.aligned.m16n8k16.row.col.f32.f16.f16.f32 "         \
        "{%0,%1,%2,%3}, {%4,%5,%6,%7}, {%8,%9}, {%0,%1,%2,%3};"               \
        : "+f"((c)[0]), "+f"((c)[1]), "+f"((c)[2]), "+f"((c)[3])              \
        : "r"((a)[0]), "r"((a)[1]), "r"((a)[2]), "r"((a)[3]),                 \
          "r"(b0), "r"(b1))
#define LDSM4(r0, r1, r2, r3, addr)                                           \
    asm volatile("ldmatrix.sync.aligned.m8n8.x4.shared.b16 {%0,%1,%2,%3}, [%4];" \
        : "=r"(r0), "=r"(r1), "=r"(r2), "=r"(r3) : "r"(addr))
#define CPA16(dst, src) \
    asm volatile("cp.async.cg.shared.global [%0], [%1], 16;" :: "r"(dst), "l"(src) : "memory")
#define CP_COMMIT() asm volatile("cp.async.commit_group;" ::: "memory")
#define CP_WAIT1()  asm volatile("cp.async.wait_group 1;" ::: "memory")

// ---------------- prepass 1: split emb -> g_eh/g_el + ||e||^2 ----------------
__global__ void vq_prep_e(const float* __restrict__ emb) {
    int gw = (blockIdx.x * blockDim.x + threadIdx.x) >> 5, lane = threadIdx.x & 31;
    if (gw >= KCODES) return;
    const float* row = emb + (size_t)gw * DIM;
    const int d0 = lane * 8;
    float4 v0 = *reinterpret_cast<const float4*>(row + d0);
    float4 v1 = *reinterpret_cast<const float4*>(row + d0 + 4);
    uint4 h, l;
    split2(v0.x, v0.y, h.x, l.x);
    split2(v0.z, v0.w, h.y, l.y);
    split2(v1.x, v1.y, h.z, l.z);
    split2(v1.z, v1.w, h.w, l.w);
    *reinterpret_cast<uint4*>(g_eh + (size_t)gw * DIM + d0) = h;
    *reinterpret_cast<uint4*>(g_el + (size_t)gw * DIM + d0) = l;
    float s = v0.x*v0.x + v0.y*v0.y + v0.z*v0.z + v0.w*v0.w
            + v1.x*v1.x + v1.y*v1.y + v1.z*v1.z + v1.w*v1.w;
    #pragma unroll
    for (int o = 16; o; o >>= 1) s += __shfl_xor_sync(0xFFFFFFFFu, s, o);
    if (lane == 0) g_en2[gw] = s;
}

// ---------------- prepass 2: transpose+split z -> g_zh/g_zl [n][d] ----------------
__global__ void vq_prep_z(const float* __restrict__ z) {
    __shared__ float t[32][33];
    const int bx = blockIdx.x, by = blockIdx.y, bz = blockIdx.z;
    const int tx = threadIdx.x, ty = threadIdx.y;
    const float* src = z + (size_t)bz * DIM * HW + (size_t)(by * 32) * HW + bx * 32;
    #pragma unroll
    for (int j = 0; j < 4; j++) { int rr = ty + j * 8; t[rr][tx] = src[(size_t)rr * HW + tx]; }
    __syncthreads();
    const int tid = ty * 32 + tx;
    #pragma unroll
    for (int it = 0; it < 2; it++) {
        int slot = tid + it * 256;
        int nl = slot >> 4, p = slot & 15;
        float x0 = t[2 * p][nl], x1 = t[2 * p + 1][nl];
        uint32_t h2, l2; split2(x0, x1, h2, l2);
        size_t n = (size_t)bz * HW + bx * 32 + nl;
        reinterpret_cast<uint32_t*>(g_zh)[n * 128 + by * 16 + p] = h2;
        reinterpret_cast<uint32_t*>(g_zl)[n * 128 + by * 16 + p] = l2;
    }
}

// ---------------- gemm: C16 = fp16(en2_k - 2 * zhi . ehi^T) ----------------
__device__ __forceinline__ void b_cpa(int c, uint32_t dstB, int tid) {
    const int nc = c >> 1, kh = c & 1;
    const __half* src = g_eh + (size_t)(nc * 128) * DIM + kh * 128;
    #pragma unroll
    for (int q = 0; q < 8; q++) {
        int idx = tid + q * 256;
        int n = idx >> 4, j = idx & 15;
        CPA16(dstB + n * 272 + j * 16, src + (size_t)n * DIM + j * 8);
    }
}

__global__ __launch_bounds__(256, 1)
void vq_gemm(float* __restrict__ dummy) {
    extern __shared__ __align__(16) uint32_t sw[];
    float* es = reinterpret_cast<float*>(sw + OFF_ES);
    const int tid = threadIdx.x, wid = tid >> 5, lane = tid & 31;
    const int wm = wid & 3, wn = wid >> 2;
    const int tig = lane & 3, grp = lane >> 2;
    const int n0 = blockIdx.x * MT;

    const uint32_t sbase = smem_u32(sw);
    const uint32_t aBase = sbase;
    const uint32_t bBase = sbase + OFF_B * 4;

    // group0: A tile + B chunk 0
    #pragma unroll
    for (int q = 0; q < 16; q++) {
        int idx = tid + q * 256;
        int m = idx >> 5, j = idx & 31;
        CPA16(aBase + m * 528 + j * 16, g_zh + (size_t)(n0 + m) * DIM + j * 8);
    }
    b_cpa(0, bBase, tid);
    CP_COMMIT();
    b_cpa(1, bBase + BSTG_W * 4, tid);
    CP_COMMIT();

    for (int i = tid; i < KCODES; i += 256) es[i] = g_en2[i];

    // ldmatrix lane addresses
    const int mrow = wm * 32 + ((lane >> 3) & 1) * 8 + (lane & 7);
    const uint32_t aAddr = aBase + mrow * 528 + (lane >> 4) * 16;
    const int nrow = wn * 64 + ((lane >> 4) << 3) + (lane & 7);
    const uint32_t bAddr0 = bBase + nrow * 272 + ((lane >> 3) & 1) * 16;

    float acc[2][8][4];

    #pragma unroll 1
    for (int c = 0; c < 16; c++) {
        const int nc = c >> 1, st = c & 1;
        CP_WAIT1();
        __syncthreads();

        if ((c & 1) == 0) {
            #pragma unroll
            for (int mt = 0; mt < 2; mt++)
                #pragma unroll
                for (int nt = 0; nt < 8; nt++)
                    #pragma unroll
                    for (int q = 0; q < 4; q++) acc[mt][nt][q] = 0.f;
        }

        #pragma unroll
        for (int kk = 0; kk < 8; kk++) {
            const uint32_t ak = (c & 1) * 256 + kk * 32;
            uint32_t ah[2][4];
            #pragma unroll
            for (int mt = 0; mt < 2; mt++)
                LDSM4(ah[mt][0], ah[mt][1], ah[mt][2], ah[mt][3],
                      aAddr + mt * (16 * 528) + ak);
            const uint32_t bk = st * (BSTG_W * 4) + kk * 32;
            #pragma unroll
            for (int ntp = 0; ntp < 4; ntp++) {
                uint32_t bh[4];
                LDSM4(bh[0], bh[1], bh[2], bh[3], bAddr0 + bk + ntp * (16 * 272));
                #pragma unroll
                for (int hf = 0; hf < 2; hf++) {
                    const int nt = ntp * 2 + hf;
                    #pragma unroll
                    for (int mt = 0; mt < 2; mt++)
                        MMA16(acc[mt][nt], ah[mt], bh[hf * 2], bh[hf * 2 + 1]);
                }
            }
        }
        __syncthreads();   // everyone done reading B stage st

        if (c & 1) {
            // epilogue: s = en2 - 2*acc -> fp16 -> C smem -> coalesced STG
            #pragma unroll
            for (int mt = 0; mt < 2; mt++) {
                const int rbase = wm * 32 + mt * 16 + grp;
                #pragma unroll
                for (int nt = 0; nt < 8; nt++) {
                    const int col = wn * 64 + nt * 8 + tig * 2;
                    const float e0 = es[nc * 128 + col], e1 = es[nc * 128 + col + 1];
                    const int cw = wn * 32 + nt * 4 + tig;
                    __half2 p01 = __floats2half2_rn(fmaf(-2.f, acc[mt][nt][0], e0),
                                                    fmaf(-2.f, acc[mt][nt][1], e1));
                    __half2 p23 = __floats2half2_rn(fmaf(-2.f, acc[mt][nt][2], e0),
                                                    fmaf(-2.f, acc[mt][nt][3], e1));
                    sw[OFF_C + rbase * 68 + cw]       = *reinterpret_cast<uint32_t*>(&p01);
                    sw[OFF_C + (rbase + 8) * 68 + cw] = *reinterpret_cast<uint32_t*>(&p23);
                }
            }
            __syncthreads();
            #pragma unroll
            for (int q = 0; q < 8; q++) {
                int idx = tid + q * 256;
                int rr = idx >> 4, seg = idx & 15;
                uint4 v = *reinterpret_cast<const uint4*>(sw + OFF_C + rr * 68 + seg * 4);
                *reinterpret_cast<uint4*>(g_c16 + (size_t)(n0 + rr) * KCODES + nc * 128 + seg * 8) = v;
            }
        }

        if (c + 2 < 16) b_cpa(c + 2, bBase + st * (BSTG_W * 4), tid);
        CP_COMMIT();
    }
}

// ---------------- select: sound windowed argmin + refinement ----------------
__global__ __launch_bounds__(256, 1)
void vq_select(const float* __restrict__ z, const float* __restrict__ emb,
               float* __restrict__ out) {
    const int tid = threadIdx.x, lane = tid & 31;
    const int r = blockIdx.x * 8 + (tid >> 5);

    // ||z_r||^2 from splits (exact to 2^-22 rel; covered by slack)
    const uint4 zh4 = *reinterpret_cast<const uint4*>(g_zh + (size_t)r * DIM + lane * 8);
    const uint4 zl4 = *reinterpret_cast<const uint4*>(g_zl + (size_t)r * DIM + lane * 8);
    float zp = 0.f;
    {
        const __half2* hh = reinterpret_cast<const __half2*>(&zh4);
        const __half2* ll = reinterpret_cast<const __half2*>(&zl4);
        #pragma unroll
        for (int t = 0; t < 4; t++) {
            float2 h = __half22float2(hh[t]), l = __half22float2(ll[t]);
            float a = h.x + l.x, bq = h.y + l.y;
            zp = fmaf(a, a, zp); zp = fmaf(bq, bq, zp);
        }
    }
    #pragma unroll
    for (int o = 16; o; o >>= 1) zp += __shfl_xor_sync(0xFFFFFFFFu, zp, o);
    const float zn2 = zp;

    // 32 scores per lane: k = j*256 + lane*8 + i
    uint4 sv[4];
    float svf[4][8];
    #pragma unroll
    for (int j = 0; j < 4; j++)
        sv[j] = *reinterpret_cast<const uint4*>(g_c16 + (size_t)r * KCODES + j * 256 + lane * 8);

    // pass 1: U = min_k (s_k + W_k)
    float U = 3.4e38f;
    #pragma unroll
    for (int j = 0; j < 4; j++) {
        const __half2* sh = reinterpret_cast<const __half2*>(&sv[j]);
        #pragma unroll
        for (int t = 0; t < 4; t++) {
            float2 s2 = __half22float2(sh[t]);
            svf[j][t * 2] = s2.x; svf[j][t * 2 + 1] = s2.y;
            float e0 = __ldg(g_en2 + j * 256 + lane * 8 + t * 2);
            float e1 = __ldg(g_en2 + j * 256 + lane * 8 + t * 2 + 1);
            float w0 = fmaf(C2W, fabsf(s2.x), fmaf(C1W, zn2 + e0, C3W));
            float w1 = fmaf(C2W, fabsf(s2.y), fmaf(C1W, zn2 + e1, C3W));
            U = fminf(U, fminf(s2.x + w0, s2.y + w1));
        }
    }
    #pragma unroll
    for (int o = 16; o; o >>= 1) U = fminf(U, __shfl_xor_sync(0xFFFFFFFFu, U, o));

    // pass 2: candidate flags (s_k - W_k <= U)
    uint32_t mask = 0;
    #pragma unroll
    for (int j = 0; j < 4; j++) {
        #pragma unroll
        for (int t = 0; t < 8; t++) {
            float s = svf[j][t];
            float e = __ldg(g_en2 + j * 256 + lane * 8 + t);
            float w = fmaf(C2W, fabsf(s), fmaf(C1W, zn2 + e, C3W));
            if (s - w <= U) mask |= 1u << (j * 8 + t);
        }
    }
    int cnt = __popc(mask);
    #pragma unroll
    for (int o = 16; o; o >>= 1) cnt += __shfl_xor_sync(0xFFFFFFFFu, cnt, o);

    int best;
    if (cnt == 1) {
        uint32_t bal = __ballot_sync(0xFFFFFFFFu, mask != 0);
        int L = __ffs(bal) - 1;
        uint32_t m = __shfl_sync(0xFFFFFFFFu, mask, L);
        int bit = __ffs(m) - 1;
        best = (bit >> 3) * 256 + L * 8 + (bit & 7);
    } else {
        // exact fp32 refinement over candidates, ascending k
        const int bb = r >> 10, hw = r & 1023;
        const float* zr = z + (size_t)bb * DIM * HW + hw;
        float zo[8];
        #pragma unroll
        for (int t = 0; t < 8; t++) zo[t] = __ldg(zr + (size_t)(lane * 8 + t) * HW);
        float bv = 3.4e38f; int bk = 0;
        for (int j = 0; j < 4; j++) {
            uint32_t bal = __ballot_sync(0xFFFFFFFFu, (mask >> (j * 8)) & 0xFFu);
            while (bal) {
                int L = __ffs(bal) - 1; bal &= bal - 1;
                uint32_t m = (__shfl_sync(0xFFFFFFFFu, mask, L) >> (j * 8)) & 0xFFu;
                while (m) {
                    int i = __ffs(m) - 1; m &= m - 1;
                    int k = j * 256 + L * 8 + i;
                    const float4* ep = reinterpret_cast<const float4*>(emb + (size_t)k * DIM + lane * 8);
                    float4 ea = __ldg(ep), eb = __ldg(ep + 1);
                    float d = zo[0]*ea.x + zo[1]*ea.y + zo[2]*ea.z + zo[3]*ea.w
                            + zo[4]*eb.x + zo[5]*eb.y + zo[6]*eb.z + zo[7]*eb.w;
                    #pragma unroll
                    for (int o = 16; o; o >>= 1) d += __shfl_xor_sync(0xFFFFFFFFu, d, o);
                    float sx = __ldg(g_en2 + k) - 2.f * d;
                    if (sx < bv) { bv = sx; bk = k; }
                }
            }
        }
        best = bk;
    }
    if (lane == 0) {
        g_codes[r] = best;
        out[CODES_OFF + r] = (float)best;
    }
}

// ---------------- gather z_q + loss ----------------
__global__ __launch_bounds__(256, 1)
void vq_gather(const float* __restrict__ z, const float* __restrict__ emb,
               float* __restrict__ out) {
    __shared__ float red[8];
    const int tid = threadIdx.x, wid = tid >> 5, lane = tid & 31;
    const int n0 = blockIdx.x * MT;
    const int b = n0 >> 10, hw0 = n0 & (HW - 1);
    const int nl = tid & 127, half = tid >> 7;
    const int code = __ldg(g_codes + n0 + nl);
    const float4* er = reinterpret_cast<const float4*>(emb + (size_t)code * DIM);
    float* zq = out + (size_t)b * DIM * HW + hw0 + nl;
    const float* zr = z + (size_t)b * DIM * HW + hw0 + nl;
    float lsum = 0.f;
    #pragma unroll 4
    for (int d4 = half; d4 < 64; d4 += 2) {
        float4 e = __ldg(er + d4);
        const int o0 = (d4 * 4) * HW;
        float z0 = zr[o0], z1 = zr[o0 + HW], z2 = zr[o0 + 2 * HW], z3 = zr[o0 + 3 * HW];
        zq[o0] = e.x; zq[o0 + HW] = e.y; zq[o0 + 2 * HW] = e.z; zq[o0 + 3 * HW] = e.w;
        float d0 = e.x - z0, d1 = e.y - z1, d2 = e.z - z2, d3 = e.w - z3;
        lsum = fmaf(d0, d0, lsum); lsum = fmaf(d1, d1, lsum);
        lsum = fmaf(d2, d2, lsum); lsum = fmaf(d3, d3, lsum);
    }
    #pragma unroll
    for (int o = 16; o; o >>= 1) lsum += __shfl_xor_sync(0xFFFFFFFFu, lsum, o);
    if (lane == 0) red[wid] = lsum;
    __syncthreads();
    if (tid == 0) {
        float s = 0.f;
        #pragma unroll
        for (int w = 0; w < 8; w++) s += red[w];
        g_partials[blockIdx.x] = s;
    }
}

// ---------------- finalize ----------------
__global__ void vq_fin(float* __restrict__ out) {
    if (threadIdx.x == 0 && blockIdx.x == 0) {
        float s = 0.f;
        for (int i = 0; i < GBLOCKS; i++) s += g_partials[i];
        out[LOSS_OFF] = 1.25f * s / (float)ZQ_ELEMS;
    }
}

extern "C" void kernel_launch(void* const* d_in, const int* in_sizes, int n_in,
                              void* d_out, int out_size) {
    const float* z   = (const float*)d_in[0];
    const float* emb = (const float*)d_in[1];
    if (n_in >= 2 && in_sizes[0] == KCODES * DIM) { const float* t = z; z = emb; emb = t; }
    float* out = (float*)d_out;

    cudaFuncSetAttribute(vq_gemm, cudaFuncAttributeMaxDynamicSharedMemorySize, SMEM_BYTES);
    vq_prep_e<<<(KCODES * 32 + 255) / 256, 256>>>(emb);
    vq_prep_z<<<dim3(32, 8, 32), dim3(32, 8)>>>(z);
    vq_gemm<<<GBLOCKS, 256, SMEM_BYTES>>>(out);
    vq_select<<<NTOT / 8, 256>>>(z, emb, out);
    vq_gather<<<GBLOCKS, 256>>>(z, emb, out);
    vq_fin<<<1, 32>>>(out);
}